// round 1
// baseline (speedup 1.0000x reference)
#include <cuda_runtime.h>
#include <math.h>

#define B 64
#define C 256
#define KTOP 8
#define NT 64
#define NMAX 20000

// -------- device scratch (no allocations allowed) --------
__device__ float g_qn[B * C];          // normalized query
__device__ float g_sinv[NMAX];         // 1/max(||s||, eps)
__device__ float g_sims[B * NMAX];     // similarity matrix
__device__ int   g_topidx[B * KTOP];   // top-k indices per batch row

// ======================= K1a: normalize query rows =======================
__global__ void qnorm_kernel(const float* __restrict__ q) {
    int b = blockIdx.x, t = threadIdx.x;
    float v = q[b * C + t];
    float ss = v * v;
    #pragma unroll
    for (int o = 16; o; o >>= 1) ss += __shfl_xor_sync(~0u, ss, o);
    __shared__ float ws[8];
    __shared__ float sc;
    if ((t & 31) == 0) ws[t >> 5] = ss;
    __syncthreads();
    if (t == 0) {
        float s = 0.f;
        #pragma unroll
        for (int i = 0; i < 8; i++) s += ws[i];
        sc = 1.f / fmaxf(sqrtf(s), 1e-12f);
    }
    __syncthreads();
    g_qn[b * C + t] = v * sc;
}

// ======================= K1b: summary inverse norms ======================
__global__ void sinv_kernel(const float* __restrict__ s, int n) {
    int warp = (blockIdx.x * blockDim.x + threadIdx.x) >> 5;
    int lane = threadIdx.x & 31;
    if (warp >= n) return;
    const float4* row = (const float4*)(s + (size_t)warp * C);
    float ss = 0.f;
    #pragma unroll
    for (int r = 0; r < 2; r++) {
        float4 v = row[lane + 32 * r];
        ss += v.x * v.x + v.y * v.y + v.z * v.z + v.w * v.w;
    }
    #pragma unroll
    for (int o = 16; o; o >>= 1) ss += __shfl_xor_sync(~0u, ss, o);
    if (lane == 0) g_sinv[warp] = 1.f / fmaxf(sqrtf(ss), 1e-12f);
}

// ======================= K2: sims = qn @ s^T * sinv ======================
// Block tile: 64 (all B) x 128 N. 256 threads, each computes 4x8.
#define TN 128
#define KC 32
__global__ void sims_kernel(const float* __restrict__ summ, int n) {
    __shared__ float Qs[KC * 65];   // [i][b], padded
    __shared__ float Ss[KC * 129];  // [i][n], padded
    int tid = threadIdx.x;
    int ng = tid & 15, bg = tid >> 4;
    int n0 = blockIdx.x * TN;
    float acc[4][8];
    #pragma unroll
    for (int a = 0; a < 4; a++)
        #pragma unroll
        for (int c = 0; c < 8; c++) acc[a][c] = 0.f;

    for (int kc = 0; kc < C; kc += KC) {
        #pragma unroll
        for (int r = 0; r < 8; r++) {            // 2048 q floats
            int idx = tid + 256 * r;
            int b = idx >> 5, i = idx & 31;
            Qs[i * 65 + b] = g_qn[b * C + kc + i];
        }
        #pragma unroll
        for (int r = 0; r < 16; r++) {           // 4096 s floats
            int idx = tid + 256 * r;
            int nn = idx >> 5, i = idx & 31;
            int ngl = n0 + nn;
            Ss[i * 129 + nn] = (ngl < n) ? summ[(size_t)ngl * C + kc + i] : 0.f;
        }
        __syncthreads();
        #pragma unroll
        for (int i = 0; i < KC; i++) {
            float qv[4], sv[8];
            #pragma unroll
            for (int a = 0; a < 4; a++) qv[a] = Qs[i * 65 + bg + 16 * a];
            #pragma unroll
            for (int c = 0; c < 8; c++) sv[c] = Ss[i * 129 + ng + 16 * c];
            #pragma unroll
            for (int a = 0; a < 4; a++)
                #pragma unroll
                for (int c = 0; c < 8; c++) acc[a][c] = fmaf(qv[a], sv[c], acc[a][c]);
        }
        __syncthreads();
    }
    #pragma unroll
    for (int c = 0; c < 8; c++) {
        int nn = n0 + ng + 16 * c;
        if (nn < n) {
            float si = g_sinv[nn];
            #pragma unroll
            for (int a = 0; a < 4; a++) {
                int b = bg + 16 * a;
                g_sims[(size_t)b * n + nn] = acc[a][c] * si;
            }
        }
    }
}

// ======================= K3: exact top-8 per batch row ===================
__global__ void topk_kernel(int n) {
    int b = blockIdx.x, tid = threadIdx.x;
    const float* row = g_sims + (size_t)b * n;
    float tv[KTOP];
    int ti[KTOP];
    #pragma unroll
    for (int i = 0; i < KTOP; i++) { tv[i] = -1e30f; ti[i] = 0x7fffffff; }
    for (int j = tid; j < n; j += 256) {
        float v = row[j];
        if (v > tv[KTOP - 1]) {
            int pos = KTOP;
            while (pos > 0 && v > tv[pos - 1]) pos--;
            for (int i = KTOP - 1; i > pos; i--) { tv[i] = tv[i - 1]; ti[i] = ti[i - 1]; }
            tv[pos] = v; ti[pos] = j;
        }
    }
    __shared__ float sv[2048];
    __shared__ int   si[2048];
    __shared__ float rv[256];
    __shared__ int   ri[256];
    __shared__ int   rp[256];
    #pragma unroll
    for (int i = 0; i < KTOP; i++) { sv[tid * 8 + i] = tv[i]; si[tid * 8 + i] = ti[i]; }
    __syncthreads();
    for (int k = 0; k < KTOP; k++) {
        float best = -1e30f; int bi = 0x7fffffff; int bp = tid * 8;
        #pragma unroll
        for (int s = 0; s < 8; s++) {
            int p = tid * 8 + s;
            float v = sv[p]; int id = si[p];
            if (v > best || (v == best && id < bi)) { best = v; bi = id; bp = p; }
        }
        rv[tid] = best; ri[tid] = bi; rp[tid] = bp;
        __syncthreads();
        for (int off = 128; off; off >>= 1) {
            if (tid < off) {
                float v2 = rv[tid + off]; int i2 = ri[tid + off];
                if (v2 > rv[tid] || (v2 == rv[tid] && i2 < ri[tid])) {
                    rv[tid] = v2; ri[tid] = i2; rp[tid] = rp[tid + off];
                }
            }
            __syncthreads();
        }
        if (tid == 0) { g_topidx[b * KTOP + k] = ri[0]; sv[rp[0]] = -1e30f; }
        __syncthreads();
    }
}

// =========== K4: fused gather + Linear + LayerNorm + gate ===============
// One block per (b, k). 64 tokens x 256 outputs. 256 threads: 16 token-groups
// (4 tokens each) x 16 j-groups (16 j each, stride 16).
#define SMEM_K4 ((64 * 256 + 32 * 257) * 4)
__global__ void proj_ln_kernel(const float* __restrict__ tmpl,
                               const float* __restrict__ wproj,
                               const float* __restrict__ bproj,
                               const float* __restrict__ gamma,
                               const float* __restrict__ beta,
                               const float* __restrict__ glog,
                               float* __restrict__ out) {
    extern __shared__ float sm[];
    float* Xs = sm;                 // [64][256]
    float* Ws = sm + 64 * 256;      // [32][257] padded, i-major
    int tid = threadIdx.x;
    int blk = blockIdx.x;
    int b = blk >> 3, k = blk & 7;
    int bank = g_topidx[b * KTOP + k];

    // gather the template tile (64 x 256 fp32, float4 coalesced)
    const float4* src = (const float4*)(tmpl + ((size_t)bank * NT) * C);
    float4* xd = (float4*)Xs;
    #pragma unroll
    for (int r = 0; r < 16; r++) xd[tid + 256 * r] = src[tid + 256 * r];

    int jg = tid & 15, tg = tid >> 4;
    float acc[4][16];
    #pragma unroll
    for (int t = 0; t < 4; t++)
        #pragma unroll
        for (int jj = 0; jj < 16; jj++) acc[t][jj] = 0.f;

    for (int kc = 0; kc < C; kc += 32) {
        __syncthreads();  // protect Ws (and first-iter Xs) before overwrite/use
        #pragma unroll
        for (int r = 0; r < 8; r++) {            // 2048 float4 of W chunk
            int v = tid + 256 * r;
            int j = v >> 3, i4 = v & 7;
            float4 w4 = *(const float4*)(wproj + (size_t)j * C + kc + i4 * 4);
            Ws[(i4 * 4 + 0) * 257 + j] = w4.x;
            Ws[(i4 * 4 + 1) * 257 + j] = w4.y;
            Ws[(i4 * 4 + 2) * 257 + j] = w4.z;
            Ws[(i4 * 4 + 3) * 257 + j] = w4.w;
        }
        __syncthreads();
        #pragma unroll
        for (int i = 0; i < 32; i++) {
            float xv[4], wv[16];
            #pragma unroll
            for (int t = 0; t < 4; t++) xv[t] = Xs[(tg * 4 + t) * C + kc + i];
            #pragma unroll
            for (int jj = 0; jj < 16; jj++) wv[jj] = Ws[i * 257 + jg + 16 * jj];
            #pragma unroll
            for (int t = 0; t < 4; t++)
                #pragma unroll
                for (int jj = 0; jj < 16; jj++)
                    acc[t][jj] = fmaf(xv[t], wv[jj], acc[t][jj]);
        }
    }

    float gate = 1.f / (1.f + expf(-glog[0]));
    float bias[16], gam[16], bet[16];
    #pragma unroll
    for (int jj = 0; jj < 16; jj++) {
        int j = jg + 16 * jj;
        bias[jj] = bproj[j]; gam[jj] = gamma[j]; bet[jj] = beta[j];
    }
    #pragma unroll
    for (int t = 0; t < 4; t++) {
        float h[16];
        float s1 = 0.f, s2 = 0.f;
        #pragma unroll
        for (int jj = 0; jj < 16; jj++) {
            h[jj] = acc[t][jj] + bias[jj];
            s1 += h[jj]; s2 += h[jj] * h[jj];
        }
        // reduce across the 16 j-lanes (contiguous within warp)
        #pragma unroll
        for (int o = 1; o < 16; o <<= 1) {
            s1 += __shfl_xor_sync(~0u, s1, o);
            s2 += __shfl_xor_sync(~0u, s2, o);
        }
        float mu = s1 * (1.f / 256.f);
        float var = s2 * (1.f / 256.f) - mu * mu;
        float rs = rsqrtf(var + 1e-5f);
        int tok = tg * 4 + t;
        float* orow = out + (((size_t)b * (KTOP * NT)) + (size_t)k * NT + tok) * C;
        #pragma unroll
        for (int jj = 0; jj < 16; jj++) {
            int j = jg + 16 * jj;
            orow[j] = ((h[jj] - mu) * rs * gam[jj] + bet[jj]) * gate;
        }
    }
}

// ======================= K5: gate output tail ============================
__global__ void gate_kernel(const float* __restrict__ glog, float* __restrict__ out,
                            int out_size) {
    float gate = 1.f / (1.f + expf(-glog[0]));
    int t = threadIdx.x;
    if (out_size >= B * KTOP * NT * C + B)
        out[B * KTOP * NT * C + t] = gate;
}

// ======================= launch ==========================================
extern "C" void kernel_launch(void* const* d_in, const int* in_sizes, int n_in,
                              void* d_out, int out_size) {
    const float* query = (const float*)d_in[0];
    const float* summ  = (const float*)d_in[1];
    const float* tmpl  = (const float*)d_in[2];
    const float* wproj = (const float*)d_in[3];
    const float* bproj = (const float*)d_in[4];
    const float* gamma = (const float*)d_in[5];
    const float* beta  = (const float*)d_in[6];
    const float* glog  = (const float*)d_in[7];
    int n = in_sizes[1] / C;
    float* out = (float*)d_out;

    cudaFuncSetAttribute(proj_ln_kernel,
                         cudaFuncAttributeMaxDynamicSharedMemorySize, SMEM_K4);

    qnorm_kernel<<<B, 256>>>(query);
    sinv_kernel<<<(n * 32 + 255) / 256, 256>>>(summ, n);
    sims_kernel<<<(n + TN - 1) / TN, 256>>>(summ, n);
    topk_kernel<<<B, 256>>>(n);
    proj_ln_kernel<<<B * KTOP, 256, SMEM_K4>>>(tmpl, wproj, bproj, gamma, beta, glog, out);
    gate_kernel<<<1, B>>>(glog, out, out_size);
}

// round 2
// speedup vs baseline: 1.0904x; 1.0904x over previous
#include <cuda_runtime.h>
#include <math.h>

#define B 64
#define C 256
#define KTOP 8
#define NT 64
#define NMAX 20000
#define TN 128
#define NBLK_MAX ((NMAX + TN - 1) / TN)        // 157
#define CAND_MAX (NBLK_MAX * 8)                // 1256 candidates per row

// -------- device scratch (no allocations allowed) --------
__device__ float g_qn[B * C];                        // normalized query
__device__ float g_sinv[NMAX];                       // 1/max(||s||, eps)
__device__ unsigned long long g_cand[B * CAND_MAX];  // per-block top-8 packed
__device__ int g_topidx[B * KTOP];                   // final top-k indices

// monotonic float->uint mapping (order-preserving for all finite floats)
__device__ __forceinline__ unsigned fmono(float f) {
    unsigned u = __float_as_uint(f);
    return (u & 0x80000000u) ? ~u : (u | 0x80000000u);
}

// ======================= K1a: normalize query rows =======================
__global__ void qnorm_kernel(const float* __restrict__ q) {
    int b = blockIdx.x, t = threadIdx.x;
    float v = q[b * C + t];
    float ss = v * v;
    #pragma unroll
    for (int o = 16; o; o >>= 1) ss += __shfl_xor_sync(~0u, ss, o);
    __shared__ float ws[8];
    __shared__ float sc;
    if ((t & 31) == 0) ws[t >> 5] = ss;
    __syncthreads();
    if (t == 0) {
        float s = 0.f;
        #pragma unroll
        for (int i = 0; i < 8; i++) s += ws[i];
        sc = 1.f / fmaxf(sqrtf(s), 1e-12f);
    }
    __syncthreads();
    g_qn[b * C + t] = v * sc;
}

// ======================= K1b: summary inverse norms ======================
__global__ void sinv_kernel(const float* __restrict__ s, int n) {
    int warp = (blockIdx.x * blockDim.x + threadIdx.x) >> 5;
    int lane = threadIdx.x & 31;
    if (warp >= n) return;
    const float4* row = (const float4*)(s + (size_t)warp * C);
    float ss = 0.f;
    #pragma unroll
    for (int r = 0; r < 2; r++) {
        float4 v = row[lane + 32 * r];
        ss += v.x * v.x + v.y * v.y + v.z * v.z + v.w * v.w;
    }
    #pragma unroll
    for (int o = 16; o; o >>= 1) ss += __shfl_xor_sync(~0u, ss, o);
    if (lane == 0) g_sinv[warp] = 1.f / fmaxf(sqrtf(ss), 1e-12f);
}

// ============== K2: sims GEMM tile + fused per-block top-8 ==============
// Block tile: 64 (all B) x 128 N. 256 threads, each computes 4x8.
// After accumulation, each half-warp (16 lanes, one bg group per row set)
// reduces its 128 values per row to a sorted top-8 candidate list.
#define KC 32

#define CE(a, b) { if (v[a] < v[b]) { unsigned long long _t = v[a]; v[a] = v[b]; v[b] = _t; } }

__global__ void sims_kernel(const float* __restrict__ summ, int n) {
    __shared__ float Qs[KC * 65];   // [i][b], padded
    __shared__ float Ss[KC * 129];  // [i][n], padded
    int tid = threadIdx.x;
    int ng = tid & 15, bg = tid >> 4;
    int n0 = blockIdx.x * TN;
    float acc[4][8];
    #pragma unroll
    for (int a = 0; a < 4; a++)
        #pragma unroll
        for (int c = 0; c < 8; c++) acc[a][c] = 0.f;

    for (int kc = 0; kc < C; kc += KC) {
        #pragma unroll
        for (int r = 0; r < 8; r++) {            // 2048 q floats
            int idx = tid + 256 * r;
            int b = idx >> 5, i = idx & 31;
            Qs[i * 65 + b] = g_qn[b * C + kc + i];
        }
        #pragma unroll
        for (int r = 0; r < 16; r++) {           // 4096 s floats
            int idx = tid + 256 * r;
            int nn = idx >> 5, i = idx & 31;
            int ngl = n0 + nn;
            Ss[i * 129 + nn] = (ngl < n) ? summ[(size_t)ngl * C + kc + i] : 0.f;
        }
        __syncthreads();
        #pragma unroll
        for (int i = 0; i < KC; i++) {
            float qv[4], sv[8];
            #pragma unroll
            for (int a = 0; a < 4; a++) qv[a] = Qs[i * 65 + bg + 16 * a];
            #pragma unroll
            for (int c = 0; c < 8; c++) sv[c] = Ss[i * 129 + ng + 16 * c];
            #pragma unroll
            for (int a = 0; a < 4; a++)
                #pragma unroll
                for (int c = 0; c < 8; c++) acc[a][c] = fmaf(qv[a], sv[c], acc[a][c]);
        }
        __syncthreads();
    }

    // load sinv for this thread's 8 columns
    float si[8];
    int nn[8];
    #pragma unroll
    for (int c = 0; c < 8; c++) {
        nn[c] = n0 + ng + 16 * c;
        si[c] = (nn[c] < n) ? g_sinv[nn[c]] : 0.f;
    }

    // per-row top-8 reduction within each half-warp
    #pragma unroll
    for (int a = 0; a < 4; a++) {
        int row = bg + 16 * a;
        unsigned long long v[8];
        #pragma unroll
        for (int c = 0; c < 8; c++) {
            if (nn[c] < n) {
                float s = acc[a][c] * si[c];
                v[c] = ((unsigned long long)fmono(s) << 32) | (unsigned)(~(unsigned)nn[c]);
            } else {
                v[c] = 0ull;  // strictly below any valid packed key
            }
        }
        // sort 8 descending (Batcher network, 19 CEs)
        CE(0,1) CE(2,3) CE(4,5) CE(6,7)
        CE(0,2) CE(1,3) CE(4,6) CE(5,7)
        CE(1,2) CE(5,6) CE(0,4) CE(3,7)
        CE(1,5) CE(2,6)
        CE(1,4) CE(3,6)
        CE(2,4) CE(3,5)
        CE(3,4)
        // merge across 16 lanes of the half-warp (xor offsets 1,2,4,8)
        #pragma unroll
        for (int o = 1; o < 16; o <<= 1) {
            unsigned long long w[8];
            #pragma unroll
            for (int c = 0; c < 8; c++) w[c] = __shfl_xor_sync(~0u, v[c], o);
            unsigned long long m[8];
            int ii = 0, jj = 0;
            #pragma unroll
            for (int k = 0; k < 8; k++) {
                bool take = v[ii] >= w[jj];
                m[k] = take ? v[ii] : w[jj];
                ii += take ? 1 : 0;
                jj += take ? 0 : 1;
            }
            #pragma unroll
            for (int c = 0; c < 8; c++) v[c] = m[c];
        }
        if (ng == 0) {
            unsigned long long* dst = g_cand + (size_t)row * CAND_MAX + (size_t)blockIdx.x * 8;
            #pragma unroll
            for (int c = 0; c < 8; c++) dst[c] = v[c];
        }
    }
}

// ======================= K3: final top-8 merge ===========================
// One block per batch row; 256 threads scan nblocks*8 candidates.
__global__ void topk_merge_kernel(int ncand) {
    int b = blockIdx.x, tid = threadIdx.x;
    const unsigned long long* cand = g_cand + (size_t)b * CAND_MAX;
    unsigned long long v[8];
    #pragma unroll
    for (int i = 0; i < 8; i++) v[i] = 0ull;
    for (int j = tid; j < ncand; j += 256) {
        unsigned long long x = cand[j];
        if (x > v[7]) {
            int pos = 8;
            #pragma unroll
            for (int i = 7; i >= 0; i--) if (x > v[i]) pos = i;
            for (int i = 7; i > pos; i--) v[i] = v[i - 1];
            v[pos] = x;
        }
    }
    // in-warp merge (32 lanes)
    #pragma unroll
    for (int o = 1; o < 32; o <<= 1) {
        unsigned long long w[8];
        #pragma unroll
        for (int c = 0; c < 8; c++) w[c] = __shfl_xor_sync(~0u, v[c], o);
        unsigned long long m[8];
        int ii = 0, jj = 0;
        #pragma unroll
        for (int k = 0; k < 8; k++) {
            bool take = v[ii] >= w[jj];
            m[k] = take ? v[ii] : w[jj];
            ii += take ? 1 : 0;
            jj += take ? 0 : 1;
        }
        #pragma unroll
        for (int c = 0; c < 8; c++) v[c] = m[c];
    }
    __shared__ unsigned long long wl[8][8];
    int warp = tid >> 5, lane = tid & 31;
    if (lane == 0)
        #pragma unroll
        for (int c = 0; c < 8; c++) wl[warp][c] = v[c];
    __syncthreads();
    if (tid == 0) {
        unsigned long long f[8];
        #pragma unroll
        for (int i = 0; i < 8; i++) f[i] = wl[0][i];
        for (int wr = 1; wr < 8; wr++) {
            for (int c = 0; c < 8; c++) {
                unsigned long long x = wl[wr][c];
                if (x > f[7]) {
                    int pos = 8;
                    #pragma unroll
                    for (int i = 7; i >= 0; i--) if (x > f[i]) pos = i;
                    for (int i = 7; i > pos; i--) f[i] = f[i - 1];
                    f[pos] = x;
                } else break;  // wl[wr] sorted descending
            }
        }
        #pragma unroll
        for (int k = 0; k < 8; k++)
            g_topidx[b * KTOP + k] = (int)(~(unsigned)(f[k] & 0xFFFFFFFFull));
    }
}

// =========== K4: fused gather + Linear + LayerNorm + gate ===============
// One block per (b, k). 64 tokens x 256 outputs. 256 threads: 16 token-groups
// (4 tokens each) x 16 j-groups (16 j each, stride 16).
#define SMEM_K4 ((64 * 256 + 32 * 257) * 4)
__global__ void proj_ln_kernel(const float* __restrict__ tmpl,
                               const float* __restrict__ wproj,
                               const float* __restrict__ bproj,
                               const float* __restrict__ gamma,
                               const float* __restrict__ beta,
                               const float* __restrict__ glog,
                               float* __restrict__ out) {
    extern __shared__ float sm[];
    float* Xs = sm;                 // [64][256]
    float* Ws = sm + 64 * 256;      // [32][257] padded, i-major
    int tid = threadIdx.x;
    int blk = blockIdx.x;
    int b = blk >> 3, k = blk & 7;
    int bank = g_topidx[b * KTOP + k];

    // gather the template tile (64 x 256 fp32, float4 coalesced)
    const float4* src = (const float4*)(tmpl + ((size_t)bank * NT) * C);
    float4* xd = (float4*)Xs;
    #pragma unroll
    for (int r = 0; r < 16; r++) xd[tid + 256 * r] = src[tid + 256 * r];

    int jg = tid & 15, tg = tid >> 4;
    float acc[4][16];
    #pragma unroll
    for (int t = 0; t < 4; t++)
        #pragma unroll
        for (int jj = 0; jj < 16; jj++) acc[t][jj] = 0.f;

    for (int kc = 0; kc < C; kc += 32) {
        __syncthreads();  // protect Ws (and first-iter Xs) before overwrite/use
        #pragma unroll
        for (int r = 0; r < 8; r++) {            // 2048 float4 of W chunk
            int v = tid + 256 * r;
            int j = v >> 3, i4 = v & 7;
            float4 w4 = *(const float4*)(wproj + (size_t)j * C + kc + i4 * 4);
            Ws[(i4 * 4 + 0) * 257 + j] = w4.x;
            Ws[(i4 * 4 + 1) * 257 + j] = w4.y;
            Ws[(i4 * 4 + 2) * 257 + j] = w4.z;
            Ws[(i4 * 4 + 3) * 257 + j] = w4.w;
        }
        __syncthreads();
        #pragma unroll
        for (int i = 0; i < 32; i++) {
            float xv[4], wv[16];
            #pragma unroll
            for (int t = 0; t < 4; t++) xv[t] = Xs[(tg * 4 + t) * C + kc + i];
            #pragma unroll
            for (int jj = 0; jj < 16; jj++) wv[jj] = Ws[i * 257 + jg + 16 * jj];
            #pragma unroll
            for (int t = 0; t < 4; t++)
                #pragma unroll
                for (int jj = 0; jj < 16; jj++)
                    acc[t][jj] = fmaf(xv[t], wv[jj], acc[t][jj]);
        }
    }

    float gate = 1.f / (1.f + expf(-glog[0]));
    float bias[16], gam[16], bet[16];
    #pragma unroll
    for (int jj = 0; jj < 16; jj++) {
        int j = jg + 16 * jj;
        bias[jj] = bproj[j]; gam[jj] = gamma[j]; bet[jj] = beta[j];
    }
    #pragma unroll
    for (int t = 0; t < 4; t++) {
        float h[16];
        float s1 = 0.f, s2 = 0.f;
        #pragma unroll
        for (int jj = 0; jj < 16; jj++) {
            h[jj] = acc[t][jj] + bias[jj];
            s1 += h[jj]; s2 += h[jj] * h[jj];
        }
        // reduce across the 16 j-lanes (contiguous within warp)
        #pragma unroll
        for (int o = 1; o < 16; o <<= 1) {
            s1 += __shfl_xor_sync(~0u, s1, o);
            s2 += __shfl_xor_sync(~0u, s2, o);
        }
        float mu = s1 * (1.f / 256.f);
        float var = s2 * (1.f / 256.f) - mu * mu;
        float rs = rsqrtf(var + 1e-5f);
        int tok = tg * 4 + t;
        float* orow = out + (((size_t)b * (KTOP * NT)) + (size_t)k * NT + tok) * C;
        #pragma unroll
        for (int jj = 0; jj < 16; jj++) {
            int j = jg + 16 * jj;
            orow[j] = ((h[jj] - mu) * rs * gam[jj] + bet[jj]) * gate;
        }
    }
}

// ======================= K5: gate output tail ============================
__global__ void gate_kernel(const float* __restrict__ glog, float* __restrict__ out,
                            int out_size) {
    float gate = 1.f / (1.f + expf(-glog[0]));
    int t = threadIdx.x;
    if (out_size >= B * KTOP * NT * C + B)
        out[B * KTOP * NT * C + t] = gate;
}

// ======================= launch ==========================================
extern "C" void kernel_launch(void* const* d_in, const int* in_sizes, int n_in,
                              void* d_out, int out_size) {
    const float* query = (const float*)d_in[0];
    const float* summ  = (const float*)d_in[1];
    const float* tmpl  = (const float*)d_in[2];
    const float* wproj = (const float*)d_in[3];
    const float* bproj = (const float*)d_in[4];
    const float* gamma = (const float*)d_in[5];
    const float* beta  = (const float*)d_in[6];
    const float* glog  = (const float*)d_in[7];
    int n = in_sizes[1] / C;
    float* out = (float*)d_out;
    int nblocks = (n + TN - 1) / TN;

    cudaFuncSetAttribute(proj_ln_kernel,
                         cudaFuncAttributeMaxDynamicSharedMemorySize, SMEM_K4);

    qnorm_kernel<<<B, 256>>>(query);
    sinv_kernel<<<(n * 32 + 255) / 256, 256>>>(summ, n);
    sims_kernel<<<nblocks, 256>>>(summ, n);
    topk_merge_kernel<<<B, 256>>>(nblocks * 8);
    proj_ln_kernel<<<B * KTOP, 256, SMEM_K4>>>(tmpl, wproj, bproj, gamma, beta, glog, out);
    gate_kernel<<<1, B>>>(glog, out, out_size);
}

// round 5
// speedup vs baseline: 1.2617x; 1.1571x over previous
#include <cuda_runtime.h>
#include <math.h>

#define B 64
#define C 256
#define KTOP 8
#define NT 64
#define NMAX 20000
#define TN 128
#define NBLK_MAX ((NMAX + TN - 1) / TN)        // 157
#define CAND_MAX (NBLK_MAX * 8)                // 1256 candidates per row

// -------- device scratch (no allocations allowed) --------
__device__ float g_qn[B * C];
__device__ float g_sinv[NMAX];
__device__ unsigned long long g_cand[B * CAND_MAX];
__device__ unsigned long long g_cand2[B * 32];
__device__ int g_topidx[B * KTOP];

typedef unsigned long long u64;

__device__ __forceinline__ unsigned fmono(float f) {
    unsigned u = __float_as_uint(f);
    return (u & 0x80000000u) ? ~u : (u | 0x80000000u);
}

// ---------------- packed f32x2 helpers ----------------
__device__ __forceinline__ u64 pack2(float lo, float hi) {
    u64 r;
    asm("mov.b64 %0, {%1, %2};" : "=l"(r) : "r"(__float_as_uint(lo)), "r"(__float_as_uint(hi)));
    return r;
}
__device__ __forceinline__ u64 dup2(float v) { return pack2(v, v); }
__device__ __forceinline__ void unpack2(u64 in, float& lo, float& hi) {
    unsigned a, b;
    asm("mov.b64 {%0, %1}, %2;" : "=r"(a), "=r"(b) : "l"(in));
    lo = __uint_as_float(a);
    hi = __uint_as_float(b);
}
__device__ __forceinline__ u64 fma2(u64 a, u64 b, u64 c) {
    u64 d;
    asm("fma.rn.f32x2 %0, %1, %2, %3;" : "=l"(d) : "l"(a), "l"(b), "l"(c));
    return d;
}

// ======================= K1a: normalize query rows =======================
__global__ void qnorm_kernel(const float* __restrict__ q) {
    int b = blockIdx.x, t = threadIdx.x;
    float v = q[b * C + t];
    float ss = v * v;
    #pragma unroll
    for (int o = 16; o; o >>= 1) ss += __shfl_xor_sync(~0u, ss, o);
    __shared__ float ws[8];
    __shared__ float sc;
    if ((t & 31) == 0) ws[t >> 5] = ss;
    __syncthreads();
    if (t == 0) {
        float s = 0.f;
        #pragma unroll
        for (int i = 0; i < 8; i++) s += ws[i];
        sc = 1.f / fmaxf(sqrtf(s), 1e-12f);
    }
    __syncthreads();
    g_qn[b * C + t] = v * sc;
}

// ======================= K1b: summary inverse norms ======================
__global__ void sinv_kernel(const float* __restrict__ s, int n) {
    int warp = (blockIdx.x * blockDim.x + threadIdx.x) >> 5;
    int lane = threadIdx.x & 31;
    if (warp >= n) return;
    const float4* row = (const float4*)(s + (size_t)warp * C);
    float ss = 0.f;
    #pragma unroll
    for (int r = 0; r < 2; r++) {
        float4 v = row[lane + 32 * r];
        ss += v.x * v.x + v.y * v.y + v.z * v.z + v.w * v.w;
    }
    #pragma unroll
    for (int o = 16; o; o >>= 1) ss += __shfl_xor_sync(~0u, ss, o);
    if (lane == 0) g_sinv[warp] = 1.f / fmaxf(sqrtf(ss), 1e-12f);
}

// ============== K2: sims GEMM tile (f32x2) + fused per-block top-8 ======
// Tile: 64 (all B) x 128 N. 256 threads. Thread (bg=tid>>4, ng=tid&15):
// rows bg+16a (a<4), column pairs j0 = 2*ng + 32*p (p<4).
#define KC 32
#define CE(a, b) { if (v[a] < v[b]) { u64 _t = v[a]; v[a] = v[b]; v[b] = _t; } }

__global__ void sims_kernel(const float* __restrict__ summ, int n) {
    __shared__ float Qs[KC * 65];                      // [i][b]
    __shared__ __align__(16) float Ss[KC * 130];       // [i][n], even stride
    int tid = threadIdx.x;
    int ng = tid & 15, bg = tid >> 4;
    int n0 = blockIdx.x * TN;
    u64 acc2[4][4];
    #pragma unroll
    for (int a = 0; a < 4; a++)
        #pragma unroll
        for (int p = 0; p < 4; p++) acc2[a][p] = 0ull;

    for (int kc = 0; kc < C; kc += KC) {
        #pragma unroll
        for (int r = 0; r < 8; r++) {
            int idx = tid + 256 * r;
            int b = idx >> 5, i = idx & 31;
            Qs[i * 65 + b] = g_qn[b * C + kc + i];
        }
        #pragma unroll
        for (int r = 0; r < 16; r++) {
            int idx = tid + 256 * r;
            int nn = idx >> 5, i = idx & 31;
            int ngl = n0 + nn;
            Ss[i * 130 + nn] = (ngl < n) ? summ[(size_t)ngl * C + kc + i] : 0.f;
        }
        __syncthreads();
        #pragma unroll
        for (int i = 0; i < KC; i++) {
            u64 qp[4], sp[4];
            #pragma unroll
            for (int a = 0; a < 4; a++) qp[a] = dup2(Qs[i * 65 + bg + 16 * a]);
            #pragma unroll
            for (int p = 0; p < 4; p++)
                sp[p] = *(const u64*)&Ss[i * 130 + 2 * ng + 32 * p];
            #pragma unroll
            for (int a = 0; a < 4; a++)
                #pragma unroll
                for (int p = 0; p < 4; p++) acc2[a][p] = fma2(qp[a], sp[p], acc2[a][p]);
        }
        __syncthreads();
    }

    // sinv + indices for this thread's 8 columns
    float si[4][2];
    int nn[4];
    #pragma unroll
    for (int p = 0; p < 4; p++) {
        nn[p] = n0 + 2 * ng + 32 * p;
        si[p][0] = (nn[p] < n) ? g_sinv[nn[p]] : 0.f;
        si[p][1] = (nn[p] + 1 < n) ? g_sinv[nn[p] + 1] : 0.f;
    }

    #pragma unroll
    for (int a = 0; a < 4; a++) {
        int row = bg + 16 * a;
        u64 v[8];
        #pragma unroll
        for (int p = 0; p < 4; p++) {
            float lo, hi;
            unpack2(acc2[a][p], lo, hi);
            v[2 * p]     = (nn[p] < n)
                ? (((u64)fmono(lo * si[p][0]) << 32) | (unsigned)(~(unsigned)nn[p])) : 0ull;
            v[2 * p + 1] = (nn[p] + 1 < n)
                ? (((u64)fmono(hi * si[p][1]) << 32) | (unsigned)(~(unsigned)(nn[p] + 1))) : 0ull;
        }
        CE(0,1) CE(2,3) CE(4,5) CE(6,7)
        CE(0,2) CE(1,3) CE(4,6) CE(5,7)
        CE(1,2) CE(5,6) CE(0,4) CE(3,7)
        CE(1,5) CE(2,6)
        CE(1,4) CE(3,6)
        CE(2,4) CE(3,5)
        CE(3,4)
        #pragma unroll
        for (int o = 1; o < 16; o <<= 1) {
            u64 w[8];
            #pragma unroll
            for (int c = 0; c < 8; c++) w[c] = __shfl_xor_sync(~0u, v[c], o);
            u64 m[8];
            int ii = 0, jj = 0;
            #pragma unroll
            for (int k = 0; k < 8; k++) {
                bool take = v[ii] >= w[jj];
                m[k] = take ? v[ii] : w[jj];
                ii += take ? 1 : 0;
                jj += take ? 0 : 1;
            }
            #pragma unroll
            for (int c = 0; c < 8; c++) v[c] = m[c];
        }
        if (ng == 0) {
            u64* dst = g_cand + (size_t)row * CAND_MAX + (size_t)blockIdx.x * 8;
            #pragma unroll
            for (int c = 0; c < 8; c++) dst[c] = v[c];
        }
    }
}

// ---------------- shared merge helpers for top-k ----------------
__device__ __forceinline__ void warp_merge8(u64* v, int width) {
    for (int o = 1; o < width; o <<= 1) {
        u64 w[8];
        #pragma unroll
        for (int c = 0; c < 8; c++) w[c] = __shfl_xor_sync(~0u, v[c], o);
        u64 m[8];
        int ii = 0, jj = 0;
        #pragma unroll
        for (int k = 0; k < 8; k++) {
            bool take = v[ii] >= w[jj];
            m[k] = take ? v[ii] : w[jj];
            ii += take ? 1 : 0;
            jj += take ? 0 : 1;
        }
        #pragma unroll
        for (int c = 0; c < 8; c++) v[c] = m[c];
    }
}

// ============ K3a: partial top-8 (grid 64 x 4, 128 threads) =============
__global__ void topk_part_kernel(int ncand) {
    int b = blockIdx.x, part = blockIdx.y, tid = threadIdx.x;
    int chunk = (ncand + 3) / 4;
    int lo = part * chunk, hi = min(lo + chunk, ncand);
    const u64* cand = g_cand + (size_t)b * CAND_MAX;
    u64 v[8];
    #pragma unroll
    for (int i = 0; i < 8; i++) v[i] = 0ull;
    for (int j = lo + tid; j < hi; j += 128) {
        u64 x = cand[j];
        if (x > v[7]) {
            int pos = 8;
            #pragma unroll
            for (int i = 7; i >= 0; i--) if (x > v[i]) pos = i;
            for (int i = 7; i > pos; i--) v[i] = v[i - 1];
            v[pos] = x;
        }
    }
    warp_merge8(v, 32);
    __shared__ u64 wl[4][8];
    int warp = tid >> 5, lane = tid & 31;
    if (lane == 0)
        #pragma unroll
        for (int c = 0; c < 8; c++) wl[warp][c] = v[c];
    __syncthreads();
    if (tid == 0) {
        u64 f[8];
        #pragma unroll
        for (int i = 0; i < 8; i++) f[i] = wl[0][i];
        for (int wr = 1; wr < 4; wr++) {
            for (int c = 0; c < 8; c++) {
                u64 x = wl[wr][c];
                if (x > f[7]) {
                    int pos = 8;
                    #pragma unroll
                    for (int i = 7; i >= 0; i--) if (x > f[i]) pos = i;
                    for (int i = 7; i > pos; i--) f[i] = f[i - 1];
                    f[pos] = x;
                } else break;
            }
        }
        u64* dst = g_cand2 + (size_t)(b * 4 + part) * 8;
        #pragma unroll
        for (int c = 0; c < 8; c++) dst[c] = f[c];
    }
}

// ============ K3b: final top-8 (grid 64, 32 threads) ====================
__global__ void topk_final_kernel() {
    int b = blockIdx.x, lane = threadIdx.x;
    u64 v[8];
    v[0] = g_cand2[(size_t)b * 32 + lane];
    #pragma unroll
    for (int i = 1; i < 8; i++) v[i] = 0ull;
    warp_merge8(v, 32);
    if (lane == 0)
        #pragma unroll
        for (int k = 0; k < KTOP; k++)
            g_topidx[b * KTOP + k] = (int)(~(unsigned)(v[k] & 0xFFFFFFFFull));
}

// ===== K4: fused gather + Linear (f32x2) + LayerNorm + gate =============
// One block per (b,k). 64 tokens x 256 outputs. Thread (tg=tid>>4, jg=tid&15):
// tokens tg*4+t, output pairs j0 = 2*jg + 32*p (p<8).
#define WS_STRIDE 258
#define SMEM_K4 ((64 * 256 + 32 * WS_STRIDE) * 4)
__global__ void __launch_bounds__(256, 2) proj_ln_kernel(
    const float* __restrict__ tmpl, const float* __restrict__ wproj,
    const float* __restrict__ bproj, const float* __restrict__ gamma,
    const float* __restrict__ beta, const float* __restrict__ glog,
    float* __restrict__ out) {
    extern __shared__ float sm[];
    float* Xs = sm;                       // [64][256]
    float* Ws = sm + 64 * 256;            // [32][258], i-major, even stride
    __shared__ __align__(16) float lnS[768];
    int tid = threadIdx.x;
    int blk = blockIdx.x;
    int bank = g_topidx[blk];

    lnS[tid] = bproj[tid];
    lnS[256 + tid] = gamma[tid];
    lnS[512 + tid] = beta[tid];

    // gather template tile (64 x 256 fp32)
    const float4* src = (const float4*)(tmpl + (size_t)bank * NT * C);
    float4* xd = (float4*)Xs;
    #pragma unroll
    for (int r = 0; r < 16; r++) xd[tid + 256 * r] = src[tid + 256 * r];

    int jg = tid & 15, tg = tid >> 4;
    u64 acc2[4][8];
    #pragma unroll
    for (int t = 0; t < 4; t++)
        #pragma unroll
        for (int p = 0; p < 8; p++) acc2[t][p] = 0ull;

    for (int kc = 0; kc < C; kc += 32) {
        __syncthreads();  // previous inner done (and Xs fill on first iter)
        #pragma unroll
        for (int r = 0; r < 8; r++) {
            int v = tid + 256 * r;
            int j = v >> 3, i4 = v & 7;
            float4 w4 = *(const float4*)(wproj + (size_t)j * C + kc + i4 * 4);
            Ws[(i4 * 4 + 0) * WS_STRIDE + j] = w4.x;
            Ws[(i4 * 4 + 1) * WS_STRIDE + j] = w4.y;
            Ws[(i4 * 4 + 2) * WS_STRIDE + j] = w4.z;
            Ws[(i4 * 4 + 3) * WS_STRIDE + j] = w4.w;
        }
        __syncthreads();
        #pragma unroll
        for (int i = 0; i < 32; i++) {
            u64 xp[4], wp[8];
            #pragma unroll
            for (int t = 0; t < 4; t++) xp[t] = dup2(Xs[(tg * 4 + t) * C + kc + i]);
            #pragma unroll
            for (int p = 0; p < 8; p++)
                wp[p] = *(const u64*)&Ws[i * WS_STRIDE + 2 * jg + 32 * p];
            #pragma unroll
            for (int t = 0; t < 4; t++)
                #pragma unroll
                for (int p = 0; p < 8; p++) acc2[t][p] = fma2(xp[t], wp[p], acc2[t][p]);
        }
    }

    float gate = 1.f / (1.f + expf(-glog[0]));
    #pragma unroll
    for (int t = 0; t < 4; t++) {
        float h[8][2];
        float s1 = 0.f, s2 = 0.f;
        #pragma unroll
        for (int p = 0; p < 8; p++) {
            int j0 = 2 * jg + 32 * p;
            float2 bb = *(const float2*)&lnS[j0];
            float lo, hi;
            unpack2(acc2[t][p], lo, hi);
            h[p][0] = lo + bb.x;
            h[p][1] = hi + bb.y;
            s1 += h[p][0] + h[p][1];
            s2 += h[p][0] * h[p][0] + h[p][1] * h[p][1];
        }
        #pragma unroll
        for (int o = 1; o < 16; o <<= 1) {
            s1 += __shfl_xor_sync(~0u, s1, o);
            s2 += __shfl_xor_sync(~0u, s2, o);
        }
        float mu = s1 * (1.f / 256.f);
        float var = s2 * (1.f / 256.f) - mu * mu;
        float rs = rsqrtf(var + 1e-5f);
        int tok = tg * 4 + t;
        float* orow = out + ((size_t)blk * NT + tok) * C;
        #pragma unroll
        for (int p = 0; p < 8; p++) {
            int j0 = 2 * jg + 32 * p;
            float2 gg = *(const float2*)&lnS[256 + j0];
            float2 be = *(const float2*)&lnS[512 + j0];
            float2 o;
            o.x = ((h[p][0] - mu) * rs * gg.x + be.x) * gate;
            o.y = ((h[p][1] - mu) * rs * gg.y + be.y) * gate;
            *(float2*)(orow + j0) = o;
        }
    }
}

// ======================= K5: gate output tail ============================
__global__ void gate_kernel(const float* __restrict__ glog, float* __restrict__ out,
                            int out_size) {
    float gate = 1.f / (1.f + expf(-glog[0]));
    int t = threadIdx.x;
    if (out_size >= B * KTOP * NT * C + B)
        out[B * KTOP * NT * C + t] = gate;
}

// ======================= launch ==========================================
extern "C" void kernel_launch(void* const* d_in, const int* in_sizes, int n_in,
                              void* d_out, int out_size) {
    const float* query = (const float*)d_in[0];
    const float* summ  = (const float*)d_in[1];
    const float* tmpl  = (const float*)d_in[2];
    const float* wproj = (const float*)d_in[3];
    const float* bproj = (const float*)d_in[4];
    const float* gamma = (const float*)d_in[5];
    const float* beta  = (const float*)d_in[6];
    const float* glog  = (const float*)d_in[7];
    int n = in_sizes[1] / C;
    float* out = (float*)d_out;
    int nblocks = (n + TN - 1) / TN;

    cudaFuncSetAttribute(proj_ln_kernel,
                         cudaFuncAttributeMaxDynamicSharedMemorySize, SMEM_K4);

    qnorm_kernel<<<B, 256>>>(query);
    sinv_kernel<<<(n * 32 + 255) / 256, 256>>>(summ, n);
    sims_kernel<<<nblocks, 256>>>(summ, n);
    topk_part_kernel<<<dim3(B, 4), 128>>>(nblocks * 8);
    topk_final_kernel<<<B, 32>>>();
    proj_ln_kernel<<<B * KTOP, 256, SMEM_K4>>>(tmpl, wproj, bproj, gamma, beta, glog, out);
    gate_kernel<<<1, B>>>(glog, out, out_size);
}